// round 7
// baseline (speedup 1.0000x reference)
#include <cuda_runtime.h>
#include <cuda_bf16.h>
#include <math.h>
#include <stdint.h>

// Problem constants (B=1)
#define S_LEN  2048
#define DMODEL 2048
#define NHEADS 16
#define HD     128
#define KVH    4
#define KVD    512   // KVH*HD

// ---------------- scratch (no allocations allowed) ----------------
__device__ float g_q[S_LEN * DMODEL];            // q proj -> normed+roped in place
__device__ float g_k[S_LEN * KVD];               // k proj -> normed+roped in place
__device__ float g_v[S_LEN * KVD];               // v proj
__device__ float g_y[S_LEN * DMODEL];            // attention output
__device__ float g_s[(size_t)NHEADS * S_LEN * S_LEN];  // scores / probs (268 MB)

// =============================================================
// bf16 split helpers
// =============================================================
__device__ __forceinline__ void mma_bf16(float* c, const uint32_t* a, const uint32_t* b) {
    asm volatile(
        "mma.sync.aligned.m16n8k16.row.col.f32.bf16.bf16.f32 "
        "{%0,%1,%2,%3}, {%4,%5,%6,%7}, {%8,%9}, {%0,%1,%2,%3};\n"
        : "+f"(c[0]), "+f"(c[1]), "+f"(c[2]), "+f"(c[3])
        : "r"(a[0]), "r"(a[1]), "r"(a[2]), "r"(a[3]),
          "r"(b[0]), "r"(b[1]));
}

// convert a float pair (x = lower-k, y = higher-k) into packed bf16x2 hi & lo
__device__ __forceinline__ void cvtpair(float x, float y, uint32_t& hi, uint32_t& lo) {
    __nv_bfloat16 hx = __float2bfloat16_rn(x);
    __nv_bfloat16 hy = __float2bfloat16_rn(y);
    float rx = x - __bfloat162float(hx);
    float ry = y - __bfloat162float(hy);
    __nv_bfloat16 lx = __float2bfloat16_rn(rx);
    __nv_bfloat16 ly = __float2bfloat16_rn(ry);
    hi = (uint32_t)__bfloat16_as_ushort(hx) | ((uint32_t)__bfloat16_as_ushort(hy) << 16);
    lo = (uint32_t)__bfloat16_as_ushort(lx) | ((uint32_t)__bfloat16_as_ushort(ly) << 16);
}

// =============================================================
// Generic batched GEMM, bf16 3-pass split (fp32-accurate ~3e-5):
//   C[z] = alpha * A[z] * op(B[z])
// A row-major [M,K]; NT mode: B row-major [N,K] (uses B^T);
//                    NN mode: B row-major [K,N].
// mode bits: 1 = NN, 2 = causal tile skip (bn>bm), 4 = triangular
// K-limit (kmax = (bm+1)*128).
// Block 128x128xBK32, 256 threads, 8 warps (2Mx4N), warp tile 64x32.
// Smem (per stage, per operand): rows of 48 u32; for k-pair c (= k>>1),
// group [hi_c, hi_{c+4}, lo_c, lo_{c+4}] is one aligned 16B quad at
//   row*48 + (c>>3)*16 + (c&3)*4   (+0 hi / +2 lo, +1 for the c+4 member)
// so every mma fragment is one LDS.128. 2-stage double buffer,
// register-staged global loads.
// =============================================================
#define SST 48
#define GSMEM_BYTES (2 * 2 * 128 * SST * 4)   // 98304

__global__ void __launch_bounds__(256)
gemm_bf16x3_kernel(const float* __restrict__ A, const float* __restrict__ B,
                   float* __restrict__ C, int M, int N, int K,
                   int lda, int ldb, int ldc,
                   size_t astride, size_t bstride, size_t cstride, int bshift,
                   float alpha, int mode)
{
    const int bm = blockIdx.y, bn = blockIdx.x, z = blockIdx.z;
    if ((mode & 2) && bn > bm) return;

    extern __shared__ uint32_t smu[];
    uint32_t* AsBase = smu;                     // [2][128][SST]
    uint32_t* BsBase = smu + 2 * 128 * SST;     // [2][128][SST]

    const int tid  = threadIdx.x;
    const int lane = tid & 31;
    const int wid  = tid >> 5;
    const int wm   = (wid >> 2) * 64;
    const int wn   = (wid & 3) * 32;
    const int g8   = lane >> 2;
    const int tig  = lane & 3;

    const float* Ab = A + z * astride + (size_t)bm * 128 * lda;
    const float* Bb = (mode & 1)
        ? B + (size_t)(z >> bshift) * bstride + bn * 128
        : B + (size_t)(z >> bshift) * bstride + (size_t)bn * 128 * ldb;

    const int kmax  = (mode & 4) ? min(K, (bm + 1) * 128) : K;
    const int nIter = kmax >> 5;

    float acc[4][4][4] = {};
    float4 ar[4], br[4];

    // ---- register-staged global loads ----
    auto loadAB = [&](int k0) {
#pragma unroll
        for (int i = 0; i < 4; i++) {
            int idx = tid + i * 256;        // 0..1023 = 128 rows x 8 float4
            int row = idx >> 3, j = idx & 7;
            ar[i] = *(const float4*)(Ab + (size_t)row * lda + k0 + j * 4);
        }
        if (mode & 1) {
#pragma unroll
            for (int i = 0; i < 2; i++) {
                int task = tid + i * 256;   // 0..511 = 16 pair-rows x 32 ncol4
                int pr = task >> 5, nc = task & 31;
                br[2 * i]     = *(const float4*)(Bb + (size_t)(k0 + 2 * pr)     * ldb + nc * 4);
                br[2 * i + 1] = *(const float4*)(Bb + (size_t)(k0 + 2 * pr + 1) * ldb + nc * 4);
            }
        } else {
#pragma unroll
            for (int i = 0; i < 4; i++) {
                int idx = tid + i * 256;
                int row = idx >> 3, j = idx & 7;
                br[i] = *(const float4*)(Bb + (size_t)row * ldb + k0 + j * 4);
            }
        }
    };

    auto stpair = [&](uint32_t* base, int row, int c, uint32_t hi, uint32_t lo) {
        int ks = c >> 3, cc = c & 7, s = cc & 3, h = cc >> 2;
        uint32_t* p = base + row * SST + ks * 16 + s * 4 + h;
        p[0] = hi; p[2] = lo;
    };

    auto storeAB = [&](int st) {
        uint32_t* As = AsBase + st * 128 * SST;
        uint32_t* Bs = BsBase + st * 128 * SST;
#pragma unroll
        for (int i = 0; i < 4; i++) {
            int idx = tid + i * 256, row = idx >> 3, j = idx & 7;
            uint32_t hi, lo;
            cvtpair(ar[i].x, ar[i].y, hi, lo); stpair(As, row, 2 * j,     hi, lo);
            cvtpair(ar[i].z, ar[i].w, hi, lo); stpair(As, row, 2 * j + 1, hi, lo);
        }
        if (mode & 1) {
#pragma unroll
            for (int i = 0; i < 2; i++) {
                int task = tid + i * 256, pr = task >> 5, nc = task & 31;
                float e0[4] = {br[2*i].x,   br[2*i].y,   br[2*i].z,   br[2*i].w};
                float e1[4] = {br[2*i+1].x, br[2*i+1].y, br[2*i+1].z, br[2*i+1].w};
#pragma unroll
                for (int e = 0; e < 4; e++) {
                    uint32_t hi, lo;
                    cvtpair(e0[e], e1[e], hi, lo);       // low half = lower k
                    stpair(Bs, nc * 4 + e, pr, hi, lo);
                }
            }
        } else {
#pragma unroll
            for (int i = 0; i < 4; i++) {
                int idx = tid + i * 256, row = idx >> 3, j = idx & 7;
                uint32_t hi, lo;
                cvtpair(br[i].x, br[i].y, hi, lo); stpair(Bs, row, 2 * j,     hi, lo);
                cvtpair(br[i].z, br[i].w, hi, lo); stpair(Bs, row, 2 * j + 1, hi, lo);
            }
        }
    };

    auto compute = [&](int st) {
        const uint32_t* As = AsBase + st * 128 * SST;
        const uint32_t* Bs = BsBase + st * 128 * SST;
#pragma unroll
        for (int g = 0; g < 2; g++) {           // two k16 steps
            uint32_t aH[4][4], aL[4][4], bH[4][2], bL[4][2];
#pragma unroll
            for (int mf = 0; mf < 4; mf++) {
                int r0 = wm + mf * 16 + g8;
                uint4 q0 = *(const uint4*)(As + r0 * SST + g * 16 + tig * 4);
                uint4 q1 = *(const uint4*)(As + (r0 + 8) * SST + g * 16 + tig * 4);
                aH[mf][0] = q0.x; aH[mf][1] = q1.x; aH[mf][2] = q0.y; aH[mf][3] = q1.y;
                aL[mf][0] = q0.z; aL[mf][1] = q1.z; aL[mf][2] = q0.w; aL[mf][3] = q1.w;
            }
#pragma unroll
            for (int nf = 0; nf < 4; nf++) {
                int n = wn + nf * 8 + g8;
                uint4 q = *(const uint4*)(Bs + n * SST + g * 16 + tig * 4);
                bH[nf][0] = q.x; bH[nf][1] = q.y;
                bL[nf][0] = q.z; bL[nf][1] = q.w;
            }
#pragma unroll
            for (int mf = 0; mf < 4; mf++)
#pragma unroll
                for (int nf = 0; nf < 4; nf++) {
                    mma_bf16(acc[mf][nf], aL[mf], bH[nf]);
                    mma_bf16(acc[mf][nf], aH[mf], bL[nf]);
                    mma_bf16(acc[mf][nf], aH[mf], bH[nf]);
                }
        }
    };

    // ---- 2-stage pipeline ----
    loadAB(0);
    storeAB(0);
    __syncthreads();
    for (int it = 0; it < nIter; ++it) {
        int cur = it & 1;
        if (it + 1 < nIter) loadAB((it + 1) << 5);
        compute(cur);
        if (it + 1 < nIter) { storeAB(cur ^ 1); __syncthreads(); }
    }

    // ---- epilogue ----
    float* Cb = C + z * cstride + (size_t)bm * 128 * ldc + bn * 128;
#pragma unroll
    for (int mf = 0; mf < 4; mf++) {
        int row0 = wm + mf * 16 + g8;
        int row1 = row0 + 8;
#pragma unroll
        for (int nf = 0; nf < 4; nf++) {
            int col = wn + nf * 8 + tig * 2;
            *(float2*)(Cb + (size_t)row0 * ldc + col) =
                make_float2(acc[mf][nf][0] * alpha, acc[mf][nf][1] * alpha);
            *(float2*)(Cb + (size_t)row1 * ldc + col) =
                make_float2(acc[mf][nf][2] * alpha, acc[mf][nf][3] * alpha);
        }
    }
}

// =============================================================
// RMSNorm + RoPE: ONE WARP per (s, head). Pure warp shuffles.
// =============================================================
__global__ void rope2_kernel(float* __restrict__ buf, int rowstride, int nheads,
                             const float* __restrict__ gain)
{
    const int w    = blockIdx.x * (blockDim.x >> 5) + (threadIdx.x >> 5);
    const int lane = threadIdx.x & 31;
    const int s = w / nheads;
    const int h = w % nheads;
    if (s >= S_LEN) return;

    float* p = buf + (size_t)s * rowstride + h * HD;

    float2 u1 = *(const float2*)(p + 2 * lane);
    float2 u2 = *(const float2*)(p + 64 + 2 * lane);

    float ss = u1.x * u1.x + u1.y * u1.y + u2.x * u2.x + u2.y * u2.y;
#pragma unroll
    for (int off = 16; off; off >>= 1)
        ss += __shfl_xor_sync(0xffffffffu, ss, off);

    const float r = rsqrtf(ss * (1.f / 128.f) + 1.1920929e-07f);
    const float g = gain ? gain[h] : 1.0f;

    float x1a = u1.x * r, x1b = u1.y * r;
    float x2a = u2.x * r, x2b = u2.y * r;

    const float kln = 9.210340371976184f / 128.f;   // ln(10000)/128
    float th0 = (float)s * expf(-(float)(2 * (2 * lane))     * kln);
    float th1 = (float)s * expf(-(float)(2 * (2 * lane + 1)) * kln);
    float c0, s0, c1, s1;
    sincosf(th0, &s0, &c0);
    sincosf(th1, &s1, &c1);

    float o1a = x1a * c0 + x2a * s0;
    float o1b = x1b * c1 + x2b * s1;
    float o2a = x2a * c0 - x1a * s0;
    float o2b = x2b * c1 - x1b * s1;

    *(float2*)(p + 2 * lane)      = make_float2(o1a * g, o1b * g);
    *(float2*)(p + 64 + 2 * lane) = make_float2(o2a * g, o2b * g);
}

// =============================================================
// Softmax per (row i, head h) over j in [0, i]; zero tail out to
// the row's 128-tile boundary so PV's triangular K-limit is safe.
// =============================================================
__global__ void __launch_bounds__(128)
softmax_kernel()
{
    const int i = blockIdx.x;
    const int h = blockIdx.y;
    float* base = g_s + ((size_t)h * S_LEN + i) * S_LEN;
    const int n = i + 1;

    const int tid = threadIdx.x;
    const int lane = tid & 31, w = tid >> 5;
    __shared__ float red[4];

    float m = -INFINITY;
    for (int j = tid; j < n; j += 128) m = fmaxf(m, base[j]);
#pragma unroll
    for (int off = 16; off; off >>= 1)
        m = fmaxf(m, __shfl_xor_sync(0xffffffffu, m, off));
    if (lane == 0) red[w] = m;
    __syncthreads();
    m = fmaxf(fmaxf(red[0], red[1]), fmaxf(red[2], red[3]));
    __syncthreads();

    float sum = 0.f;
    for (int j = tid; j < n; j += 128) sum += expf(base[j] - m);
#pragma unroll
    for (int off = 16; off; off >>= 1)
        sum += __shfl_xor_sync(0xffffffffu, sum, off);
    if (lane == 0) red[w] = sum;
    __syncthreads();
    const float inv = 1.f / (red[0] + red[1] + red[2] + red[3]);

    for (int j = tid; j < n; j += 128) base[j] = expf(base[j] - m) * inv;

    // zero tail out to the 128-tile boundary (PV reads k < (bm+1)*128)
    const int te = ((i >> 7) + 1) << 7;
    for (int j = n + tid; j < te; j += 128) base[j] = 0.f;
}

// =============================================================
// v-direction rejection, in place on g_y. One warp per (s, h).
// =============================================================
__global__ void reject_kernel()
{
    const int w    = blockIdx.x * (blockDim.x >> 5) + (threadIdx.x >> 5);
    const int lane = threadIdx.x & 31;
    const int s = w >> 4;
    const int h = w & 15;
    if (s >= S_LEN) return;

    const int kv = h >> 2;
    float* yp = g_y + (size_t)s * DMODEL + h * HD;
    const float* vp = g_v + (size_t)s * KVD + kv * HD;

    float4 vv = *(const float4*)(vp + lane * 4);
    float4 yy = *(const float4*)(yp + lane * 4);
    float vsq = vv.x * vv.x + vv.y * vv.y + vv.z * vv.z + vv.w * vv.w;
    float yv  = yy.x * vv.x + yy.y * vv.y + yy.z * vv.z + yy.w * vv.w;
#pragma unroll
    for (int off = 16; off; off >>= 1) {
        vsq += __shfl_xor_sync(0xffffffffu, vsq, off);
        yv  += __shfl_xor_sync(0xffffffffu, yv, off);
    }
    float mx = fmaxf(sqrtf(vsq), 1e-12f);
    float c2 = yv / (mx * mx);
    yy.x -= c2 * vv.x; yy.y -= c2 * vv.y;
    yy.z -= c2 * vv.z; yy.w -= c2 * vv.w;
    *(float4*)(yp + lane * 4) = yy;
}

// =============================================================
// v output transpose: [S][KV*128] -> [KV][S][128]
// =============================================================
__global__ void v_transpose_kernel(const float* __restrict__ v, float* __restrict__ out)
{
    int idx = blockIdx.x * blockDim.x + threadIdx.x;
    if (idx < S_LEN * KVD / 4) {
        int f = idx * 4;
        int s = f / KVD;
        int rem = f % KVD;
        int kvh = rem / HD;
        int d = rem % HD;
        float4 val = *(const float4*)(v + f);
        *(float4*)(out + (size_t)kvh * S_LEN * HD + (size_t)s * HD + d) = val;
    }
}

// =============================================================
// launch — input identification by size signature (see R2 notes).
// =============================================================
extern "C" void kernel_launch(void* const* d_in, const int* in_sizes, int n_in,
                              void* d_out, int out_size)
{
    int big[3], nbig = 0;
    int med[2], nmed = 0;
    int gidx = -1;
    for (int i = 0; i < n_in && i < 6; i++) {
        int sz = in_sizes[i];
        if (sz == NHEADS)                 gidx = i;
        else if (sz == S_LEN * KVD)       { if (nmed < 2) med[nmed++] = i; }
        else                              { if (nbig < 3) big[nbig++] = i; }
    }
    int ix, iwq, iwk, iwv, iwp, ig;
    ig  = (gidx >= 0) ? gidx : 5;
    iwk = (nmed > 0) ? med[0] : 2;
    iwv = (nmed > 1) ? med[1] : 3;
    if (ig == 5) {          // dict / signature order: x, Wq, ..., Wp
        ix  = (nbig > 0) ? big[0] : 0;
        iwq = (nbig > 1) ? big[1] : 1;
        iwp = (nbig > 2) ? big[2] : 4;
    } else {                // alphabetical: Wk, Wp, Wq, Wv, q_gain, x
        iwp = (nbig > 0) ? big[0] : 1;
        iwq = (nbig > 1) ? big[1] : 2;
        ix  = (nbig > 2) ? big[2] : 5;
    }

    const float* x  = (const float*)d_in[ix];
    const float* Wq = (const float*)d_in[iwq];
    const float* Wk = (const float*)d_in[iwk];
    const float* Wv = (const float*)d_in[iwv];
    const float* Wp = (const float*)d_in[iwp];
    const float* qg = (const float*)d_in[ig];
    float* out = (float*)d_out;

    float *pq, *pk, *pv, *py, *ps;
    cudaGetSymbolAddress((void**)&pq, g_q);
    cudaGetSymbolAddress((void**)&pk, g_k);
    cudaGetSymbolAddress((void**)&pv, g_v);
    cudaGetSymbolAddress((void**)&py, g_y);
    cudaGetSymbolAddress((void**)&ps, g_s);

    cudaFuncSetAttribute(gemm_bf16x3_kernel,
                         cudaFuncAttributeMaxDynamicSharedMemorySize, GSMEM_BYTES);
    (void)cudaGetLastError();   // clear any sticky state; attribute set is idempotent

    const float scale = 0.08838834764831845f;   // 1/sqrt(128)

    // projections (NT): C = A * W^T
    gemm_bf16x3_kernel<<<dim3(DMODEL / 128, S_LEN / 128, 1), 256, GSMEM_BYTES>>>(
        x, Wq, pq, S_LEN, DMODEL, DMODEL, DMODEL, DMODEL, DMODEL,
        0, 0, 0, 0, 1.0f, 0);
    gemm_bf16x3_kernel<<<dim3(KVD / 128, S_LEN / 128, 1), 256, GSMEM_BYTES>>>(
        x, Wk, pk, S_LEN, KVD, DMODEL, DMODEL, DMODEL, KVD,
        0, 0, 0, 0, 1.0f, 0);
    gemm_bf16x3_kernel<<<dim3(KVD / 128, S_LEN / 128, 1), 256, GSMEM_BYTES>>>(
        x, Wv, pv, S_LEN, KVD, DMODEL, DMODEL, DMODEL, KVD,
        0, 0, 0, 0, 1.0f, 0);

    // rmsnorm + rope (+ gain on q)
    rope2_kernel<<<(S_LEN * NHEADS) / 4, 128>>>(pq, DMODEL, NHEADS, qg);
    rope2_kernel<<<(S_LEN * KVH)    / 4, 128>>>(pk, KVD,    KVH,    nullptr);

    // scores (NT, batched over 16 heads, causal tile skip):
    //   S[h] = scale * Q[:, h*128:...] @ K[:, (h>>2)*128:...]^T
    gemm_bf16x3_kernel<<<dim3(S_LEN / 128, S_LEN / 128, NHEADS), 256, GSMEM_BYTES>>>(
        pq, pk, ps, S_LEN, S_LEN, HD, DMODEL, KVD, S_LEN,
        (size_t)HD, (size_t)HD, (size_t)S_LEN * S_LEN, 2, scale, 2);

    // softmax (causal rows)
    softmax_kernel<<<dim3(S_LEN, NHEADS), 128>>>();

    // PV (NN, batched, triangular K-limit): Y[:, h*128:] = P[h] @ V[:, (h>>2)*128:]
    gemm_bf16x3_kernel<<<dim3(HD / 128, S_LEN / 128, NHEADS), 256, GSMEM_BYTES>>>(
        ps, pv, py, S_LEN, HD, S_LEN, S_LEN, KVD, DMODEL,
        (size_t)S_LEN * S_LEN, (size_t)HD, (size_t)HD, 2, 1.0f, 1 | 4);

    // v-rejection (in place on g_y)
    reject_kernel<<<(S_LEN * NHEADS) / 4, 128>>>();

    // output projection (NT)
    gemm_bf16x3_kernel<<<dim3(DMODEL / 128, S_LEN / 128, 1), 256, GSMEM_BYTES>>>(
        py, Wp, out, S_LEN, DMODEL, DMODEL, DMODEL, DMODEL, DMODEL,
        0, 0, 0, 0, 1.0f, 0);

    // v second output
    if (out_size >= S_LEN * DMODEL + S_LEN * KVD)
        v_transpose_kernel<<<(S_LEN * KVD / 4 + 255) / 256, 256>>>(pv, out + (size_t)S_LEN * DMODEL);
}

// round 9
// speedup vs baseline: 1.6113x; 1.6113x over previous
#include <cuda_runtime.h>
#include <cuda_bf16.h>
#include <math.h>
#include <stdint.h>

#define S_LEN  2048
#define DMODEL 2048
#define NHEADS 16
#define HD     128
#define KVH    4
#define KVD    512

// ---------------- fp32 intermediates ----------------
__device__ float g_q[S_LEN * DMODEL];
__device__ float g_k[S_LEN * KVD];
__device__ float g_v[S_LEN * KVD];
__device__ float g_y[S_LEN * DMODEL];
__device__ float g_s[(size_t)NHEADS * S_LEN * S_LEN];

// ---------------- packed quad images ----------------
// Image for matrix [R][K] (K-major): quad t = r*(K/32)*8 + ch*8 + q, where
// q = ks*4+s encodes k0 = ch*32 + ks*16 + s*2; quad = {hi(k0,k0+1),
// hi(k0+8,k0+9), lo(k0,k0+1), lo(k0+8,k0+9)} (bf16x2 each).
__device__ uint4 xq_[1048576];    // x   [2048][2048]
__device__ uint4 wqq_[1048576];
__device__ uint4 wkq_[262144];
__device__ uint4 wvq_[262144];
__device__ uint4 wpq_[1048576];
__device__ uint4 qq_[1048576];    // q roped, rows h*2048+s, K=128
__device__ uint4 kq_[262144];     // k roped, rows kv*2048+s, K=128
__device__ uint4 vtq_[262144];    // V^T, rows kv*128+d, K=2048
__device__ uint4 yq_[1048576];    // y rejected [2048][2048]
__device__ uint4 pq_[16777216];   // P, rows h*2048+i, K=2048

// ---------------- helpers ----------------
__device__ __forceinline__ void cvtpair(float x, float y, uint32_t& hi, uint32_t& lo) {
    __nv_bfloat16 hx = __float2bfloat16_rn(x);
    __nv_bfloat16 hy = __float2bfloat16_rn(y);
    float rx = x - __bfloat162float(hx);
    float ry = y - __bfloat162float(hy);
    __nv_bfloat16 lx = __float2bfloat16_rn(rx);
    __nv_bfloat16 ly = __float2bfloat16_rn(ry);
    hi = (uint32_t)__bfloat16_as_ushort(hx) | ((uint32_t)__bfloat16_as_ushort(hy) << 16);
    lo = (uint32_t)__bfloat16_as_ushort(lx) | ((uint32_t)__bfloat16_as_ushort(ly) << 16);
}

__device__ __forceinline__ uint4 pack_quad(float f0, float f1, float f2, float f3) {
    uint32_t h0, l0, h1, l1;
    cvtpair(f0, f1, h0, l0);
    cvtpair(f2, f3, h1, l1);
    return make_uint4(h0, h1, l0, l1);
}

__device__ __forceinline__ uint32_t s2u(const void* p) {
    uint32_t a;
    asm("{ .reg .u64 t; cvta.to.shared.u64 t, %1; cvt.u32.u64 %0, t; }" : "=r"(a) : "l"(p));
    return a;
}

__device__ __forceinline__ void mma_bf16(float* c, const uint32_t* a, const uint32_t* b) {
    asm volatile(
        "mma.sync.aligned.m16n8k16.row.col.f32.bf16.bf16.f32 "
        "{%0,%1,%2,%3}, {%4,%5,%6,%7}, {%8,%9}, {%0,%1,%2,%3};\n"
        : "+f"(c[0]), "+f"(c[1]), "+f"(c[2]), "+f"(c[3])
        : "r"(a[0]), "r"(a[1]), "r"(a[2]), "r"(a[3]),
          "r"(b[0]), "r"(b[1]));
}

// ---------------- generic K-major pack ----------------
__global__ void pack_mat(const float* __restrict__ src, int ldk,
                         uint4* __restrict__ dst, int nCh, int totalQ)
{
    int t = blockIdx.x * 256 + threadIdx.x;
    if (t >= totalQ) return;
    int rq = nCh * 8;
    int r = t / rq;
    int G = t - r * rq;
    int ch = G >> 3, q = G & 7;
    int k0 = ch * 32 + (q >> 2) * 16 + (q & 3) * 2;
    const float* p = src + (size_t)r * ldk + k0;
    dst[t] = pack_quad(p[0], p[1], p[8], p[9]);
}

// ---------------- V^T pack: rows kv*128+d, K = sequence ----------------
__global__ void pack_vt()
{
    int t = blockIdx.x * 256 + threadIdx.x;   // 262144
    int q = t & 7, ch = (t >> 3) & 63;
    int d = (t >> 9) & 127, kv = t >> 16;
    int k0 = ch * 32 + (q >> 2) * 16 + (q & 3) * 2;
    const float* p = g_v + (size_t)k0 * KVD + kv * HD + d;
    vtq_[t] = pack_quad(p[0], p[KVD], p[8 * KVD], p[9 * KVD]);
}

// =============================================================
// bf16 3-pass GEMM, NT on packed images:  C[z] = alpha * A[z] * B[z]^T
// mode: 2 = causal tile skip (bn>bm), 4 = triangular K (nCh=(bm+1)*4)
// Tile 128x128 x 32-K chunks; 256 thr, 8 warps (2Mx4N), warp 64x32.
// Smem per stage per operand: 128 rows x 48 u32 (8 data quads + pad).
// Loader: pure cp.async 16B identity copies; 2-stage pipeline.
// =============================================================
#define SST 48
#define STAGE_U32 (2 * 128 * SST)
#define GSMEM_BYTES (2 * STAGE_U32 * 4)   // 98304

__global__ void __launch_bounds__(256, 2)
gemm_pk(const uint4* __restrict__ Aq, int aRow, size_t aZ,
        const uint4* __restrict__ Bq, int bRow, size_t bZ, int bshift,
        float* __restrict__ C, int ldc, size_t cZ,
        int nChTot, float alpha, int mode)
{
    const int bm = blockIdx.y, bn = blockIdx.x, z = blockIdx.z;
    if ((mode & 2) && bn > bm) return;
    const int nCh = (mode & 4) ? min(nChTot, (bm + 1) * 4) : nChTot;

    extern __shared__ uint32_t smu[];
    const uint32_t smA = s2u(smu);

    const int tid = threadIdx.x, lane = tid & 31, wid = tid >> 5;
    const int wm = (wid >> 2) * 64, wn = (wid & 3) * 32;
    const int g8 = lane >> 2, tig = lane & 3;

    const uint4* Ab = Aq + z * aZ + (size_t)bm * 128 * aRow;
    const uint4* Bb = Bq + (size_t)(z >> bshift) * bZ + (size_t)bn * 128 * bRow;

    float acc[4][4][4] = {};

    auto loadStage = [&](int ch, int st) {
        uint32_t base = smA + st * (STAGE_U32 * 4);
#pragma unroll
        for (int i = 0; i < 8; i++) {
            int idx = tid + i * 256;              // 0..2047
            int op = idx >> 10, rem = idx & 1023;
            int row = rem >> 3, q = rem & 7;
            const uint4* src = (op ? Bb + (size_t)row * bRow
                                   : Ab + (size_t)row * aRow) + ch * 8 + q;
            uint32_t dst = base + (uint32_t)(op * (128 * SST) + row * SST + q * 4) * 4;
            asm volatile("cp.async.cg.shared.global [%0], [%1], 16;"
                         :: "r"(dst), "l"(src) : "memory");
        }
        asm volatile("cp.async.commit_group;" ::: "memory");
    };

    auto compute = [&](int st) {
        const uint32_t* As = smu + st * STAGE_U32;
        const uint32_t* Bs = As + 128 * SST;
#pragma unroll
        for (int g = 0; g < 2; g++) {
            uint32_t aH[4][4], aL[4][4], bH[4][2], bL[4][2];
#pragma unroll
            for (int mf = 0; mf < 4; mf++) {
                int r0 = wm + mf * 16 + g8;
                uint4 q0 = *(const uint4*)(As + r0 * SST + g * 16 + tig * 4);
                uint4 q1 = *(const uint4*)(As + (r0 + 8) * SST + g * 16 + tig * 4);
                aH[mf][0] = q0.x; aH[mf][1] = q1.x; aH[mf][2] = q0.y; aH[mf][3] = q1.y;
                aL[mf][0] = q0.z; aL[mf][1] = q1.z; aL[mf][2] = q0.w; aL[mf][3] = q1.w;
            }
#pragma unroll
            for (int nf = 0; nf < 4; nf++) {
                int n = wn + nf * 8 + g8;
                uint4 q = *(const uint4*)(Bs + n * SST + g * 16 + tig * 4);
                bH[nf][0] = q.x; bH[nf][1] = q.y;
                bL[nf][0] = q.z; bL[nf][1] = q.w;
            }
#pragma unroll
            for (int mf = 0; mf < 4; mf++)
#pragma unroll
                for (int nf = 0; nf < 4; nf++) {
                    mma_bf16(acc[mf][nf], aL[mf], bH[nf]);
                    mma_bf16(acc[mf][nf], aH[mf], bL[nf]);
                    mma_bf16(acc[mf][nf], aH[mf], bH[nf]);
                }
        }
    };

    loadStage(0, 0);
    for (int it = 0; it < nCh; ++it) {
        int cur = it & 1;
        if (it + 1 < nCh) {
            loadStage(it + 1, cur ^ 1);
            asm volatile("cp.async.wait_group 1;" ::: "memory");
        } else {
            asm volatile("cp.async.wait_group 0;" ::: "memory");
        }
        __syncthreads();
        compute(cur);
        __syncthreads();
    }

    float* Cb = C + z * cZ + (size_t)bm * 128 * ldc + bn * 128;
#pragma unroll
    for (int mf = 0; mf < 4; mf++) {
        int row0 = wm + mf * 16 + g8, row1 = row0 + 8;
#pragma unroll
        for (int nf = 0; nf < 4; nf++) {
            int col = wn + nf * 8 + tig * 2;
            *(float2*)(Cb + (size_t)row0 * ldc + col) =
                make_float2(acc[mf][nf][0] * alpha, acc[mf][nf][1] * alpha);
            *(float2*)(Cb + (size_t)row1 * ldc + col) =
                make_float2(acc[mf][nf][2] * alpha, acc[mf][nf][3] * alpha);
        }
    }
}

// ---------------- RMSNorm + RoPE -> packed image (K=128 rows) ----------------
__global__ void rope2_kernel(const float* __restrict__ buf, int rowstride, int nheads,
                             const float* __restrict__ gain, uint4* __restrict__ img)
{
    __shared__ float stg[4][128];
    const int wib = threadIdx.x >> 5;
    const int w = blockIdx.x * 4 + wib;
    const int lane = threadIdx.x & 31;
    const int s = w / nheads, h = w % nheads;
    if (s >= S_LEN) return;

    const float* p = buf + (size_t)s * rowstride + h * HD;
    float2 u1 = *(const float2*)(p + 2 * lane);
    float2 u2 = *(const float2*)(p + 64 + 2 * lane);
    float ss = u1.x * u1.x + u1.y * u1.y + u2.x * u2.x + u2.y * u2.y;
#pragma unroll
    for (int off = 16; off; off >>= 1) ss += __shfl_xor_sync(0xffffffffu, ss, off);
    const float r = rsqrtf(ss * (1.f / 128.f) + 1.1920929e-07f);
    const float g = gain ? gain[h] : 1.0f;
    float x1a = u1.x * r, x1b = u1.y * r, x2a = u2.x * r, x2b = u2.y * r;
    const float kln = 9.210340371976184f / 128.f;
    float th0 = (float)s * expf(-(float)(4 * lane) * kln);
    float th1 = (float)s * expf(-(float)(4 * lane + 2) * kln);
    float c0, s0, c1, s1;
    sincosf(th0, &s0, &c0);
    sincosf(th1, &s1, &c1);
    stg[wib][2 * lane]          = (x1a * c0 + x2a * s0) * g;
    stg[wib][2 * lane + 1]      = (x1b * c1 + x2b * s1) * g;
    stg[wib][64 + 2 * lane]     = (x2a * c0 - x1a * s0) * g;
    stg[wib][64 + 2 * lane + 1] = (x2b * c1 - x1b * s1) * g;
    __syncwarp();
    // one quad per lane: rowQuads = 32
    int ch = lane >> 3, q = lane & 7;
    int k0 = ch * 32 + (q >> 2) * 16 + (q & 3) * 2;
    const float* sp = &stg[wib][0];
    img[(size_t)(h * S_LEN + s) * 32 + lane] =
        pack_quad(sp[k0], sp[k0 + 1], sp[k0 + 8], sp[k0 + 9]);
}

// ---------------- softmax -> packed P (rows h*2048+i, K=2048) ----------------
__global__ void __launch_bounds__(128)
softmax_kernel()
{
    const int i = blockIdx.x, h = blockIdx.y;
    const float* base = g_s + ((size_t)h * S_LEN + i) * S_LEN;
    const int n = i + 1;
    const int tid = threadIdx.x, lane = tid & 31, w = tid >> 5;
    __shared__ float red[4];

    float m = -INFINITY;
    for (int j = tid; j < n; j += 128) m = fmaxf(m, base[j]);
#pragma unroll
    for (int off = 16; off; off >>= 1) m = fmaxf(m, __shfl_xor_sync(0xffffffffu, m, off));
    if (lane == 0) red[w] = m;
    __syncthreads();
    m = fmaxf(fmaxf(red[0], red[1]), fmaxf(red[2], red[3]));
    __syncthreads();

    float sum = 0.f;
    for (int j = tid; j < n; j += 128) sum += expf(base[j] - m);
#pragma unroll
    for (int off = 16; off; off >>= 1) sum += __shfl_xor_sync(0xffffffffu, sum, off);
    if (lane == 0) red[w] = sum;
    __syncthreads();
    const float inv = 1.f / (red[0] + red[1] + red[2] + red[3]);

    // pack quads out to the row's 128-tile boundary (PV reads that far)
    const int nQ = ((i >> 7) + 1) * 32;
    uint4* dst = pq_ + (size_t)(h * S_LEN + i) * 512;
    for (int G = tid; G < nQ; G += 128) {
        int ch = G >> 3, q = G & 7;
        int k0 = ch * 32 + (q >> 2) * 16 + (q & 3) * 2;
        float e0 = (k0     < n) ? expf(base[k0]     - m) * inv : 0.f;
        float e1 = (k0 + 1 < n) ? expf(base[k0 + 1] - m) * inv : 0.f;
        float e2 = (k0 + 8 < n) ? expf(base[k0 + 8] - m) * inv : 0.f;
        float e3 = (k0 + 9 < n) ? expf(base[k0 + 9] - m) * inv : 0.f;
        dst[G] = pack_quad(e0, e1, e2, e3);
    }
}

// ---------------- v-rejection -> packed y image ----------------
__global__ void reject_kernel()
{
    __shared__ float stg[4][128];
    const int wib = threadIdx.x >> 5;
    const int w = blockIdx.x * 4 + wib;
    const int lane = threadIdx.x & 31;
    const int s = w >> 4, h = w & 15;
    if (s >= S_LEN) return;
    const int kv = h >> 2;
    const float* yp = g_y + (size_t)s * DMODEL + h * HD;
    const float* vp = g_v + (size_t)s * KVD + kv * HD;

    float4 vv = *(const float4*)(vp + lane * 4);
    float4 yy = *(const float4*)(yp + lane * 4);
    float vsq = vv.x * vv.x + vv.y * vv.y + vv.z * vv.z + vv.w * vv.w;
    float yv  = yy.x * vv.x + yy.y * vv.y + yy.z * vv.z + yy.w * vv.w;
#pragma unroll
    for (int off = 16; off; off >>= 1) {
        vsq += __shfl_xor_sync(0xffffffffu, vsq, off);
        yv  += __shfl_xor_sync(0xffffffffu, yv, off);
    }
    float mx = fmaxf(sqrtf(vsq), 1e-12f);
    float c2 = yv / (mx * mx);
    stg[wib][4 * lane]     = yy.x - c2 * vv.x;
    stg[wib][4 * lane + 1] = yy.y - c2 * vv.y;
    stg[wib][4 * lane + 2] = yy.z - c2 * vv.z;
    stg[wib][4 * lane + 3] = yy.w - c2 * vv.w;
    __syncwarp();
    int chl = lane >> 3, q = lane & 7;
    int k0 = chl * 32 + (q >> 2) * 16 + (q & 3) * 2;
    const float* sp = &stg[wib][0];
    yq_[(size_t)s * 512 + (h * 4 + chl) * 8 + q] =
        pack_quad(sp[k0], sp[k0 + 1], sp[k0 + 8], sp[k0 + 9]);
}

__global__ void v_transpose_kernel(float* __restrict__ out)
{
    int idx = blockIdx.x * blockDim.x + threadIdx.x;
    if (idx < S_LEN * KVD / 4) {
        int f = idx * 4;
        int s = f / KVD, rem = f % KVD;
        int kvh = rem / HD, d = rem % HD;
        float4 val = *(const float4*)(g_v + f);
        *(float4*)(out + (size_t)kvh * S_LEN * HD + (size_t)s * HD + d) = val;
    }
}

// ---------------- launch ----------------
extern "C" void kernel_launch(void* const* d_in, const int* in_sizes, int n_in,
                              void* d_out, int out_size)
{
    int big[3], nbig = 0, med[2], nmed = 0, gidx = -1;
    for (int i = 0; i < n_in && i < 6; i++) {
        int sz = in_sizes[i];
        if (sz == NHEADS) gidx = i;
        else if (sz == S_LEN * KVD) { if (nmed < 2) med[nmed++] = i; }
        else { if (nbig < 3) big[nbig++] = i; }
    }
    int ix, iwq, iwk, iwv, iwp, ig;
    ig  = (gidx >= 0) ? gidx : 5;
    iwk = (nmed > 0) ? med[0] : 2;
    iwv = (nmed > 1) ? med[1] : 3;
    if (ig == 5) { ix = big[0]; iwq = big[1]; iwp = big[2]; }
    else         { iwp = big[0]; iwq = big[1]; ix = big[2]; }

    const float* x  = (const float*)d_in[ix];
    const float* Wq = (const float*)d_in[iwq];
    const float* Wk = (const float*)d_in[iwk];
    const float* Wv = (const float*)d_in[iwv];
    const float* Wp = (const float*)d_in[iwp];
    const float* qg = (const float*)d_in[ig];
    float* out = (float*)d_out;

    float *pfq, *pfk, *pfv, *pfy, *pfs;
    cudaGetSymbolAddress((void**)&pfq, g_q);
    cudaGetSymbolAddress((void**)&pfk, g_k);
    cudaGetSymbolAddress((void**)&pfv, g_v);
    cudaGetSymbolAddress((void**)&pfy, g_y);
    cudaGetSymbolAddress((void**)&pfs, g_s);
    uint4 *ixq, *iwqq, *iwkq, *iwvq, *iwpq, *iqq, *ikq, *ivt, *iyq, *ipq;
    cudaGetSymbolAddress((void**)&ixq,  xq_);
    cudaGetSymbolAddress((void**)&iwqq, wqq_);
    cudaGetSymbolAddress((void**)&iwkq, wkq_);
    cudaGetSymbolAddress((void**)&iwvq, wvq_);
    cudaGetSymbolAddress((void**)&iwpq, wpq_);
    cudaGetSymbolAddress((void**)&iqq,  qq_);
    cudaGetSymbolAddress((void**)&ikq,  kq_);
    cudaGetSymbolAddress((void**)&ivt,  vtq_);
    cudaGetSymbolAddress((void**)&iyq,  yq_);
    cudaGetSymbolAddress((void**)&ipq,  pq_);

    cudaFuncSetAttribute(gemm_pk, cudaFuncAttributeMaxDynamicSharedMemorySize, GSMEM_BYTES);
    (void)cudaGetLastError();

    const float scale = 0.08838834764831845f;

    // one-time packs
    pack_mat<<<4096, 256>>>(x,  DMODEL, ixq,  64, 1048576);
    pack_mat<<<4096, 256>>>(Wq, DMODEL, iwqq, 64, 1048576);
    pack_mat<<<1024, 256>>>(Wk, DMODEL, iwkq, 64, 262144);
    pack_mat<<<1024, 256>>>(Wv, DMODEL, iwvq, 64, 262144);
    pack_mat<<<4096, 256>>>(Wp, DMODEL, iwpq, 64, 1048576);

    // projections (NT)
    gemm_pk<<<dim3(16, 16, 1), 256, GSMEM_BYTES>>>(ixq, 512, 0, iwqq, 512, 0, 0,
                                                   pfq, DMODEL, 0, 64, 1.0f, 0);
    gemm_pk<<<dim3(4, 16, 1), 256, GSMEM_BYTES>>>(ixq, 512, 0, iwkq, 512, 0, 0,
                                                  pfk, KVD, 0, 64, 1.0f, 0);
    gemm_pk<<<dim3(4, 16, 1), 256, GSMEM_BYTES>>>(ixq, 512, 0, iwvq, 512, 0, 0,
                                                  pfv, KVD, 0, 64, 1.0f, 0);

    // rmsnorm + rope -> packed q/k; V^T pack
    rope2_kernel<<<(S_LEN * NHEADS) / 4, 128>>>(pfq, DMODEL, NHEADS, qg, iqq);
    rope2_kernel<<<(S_LEN * KVH) / 4, 128>>>(pfk, KVD, KVH, nullptr, ikq);
    pack_vt<<<1024, 256>>>();

    // scores (causal tile skip): S[h] = scale * Qh @ Kkv^T
    gemm_pk<<<dim3(16, 16, NHEADS), 256, GSMEM_BYTES>>>(iqq, 32, 65536, ikq, 32, 65536, 2,
                                                        pfs, S_LEN, (size_t)S_LEN * S_LEN,
                                                        4, scale, 2);

    // softmax -> packed P
    softmax_kernel<<<dim3(S_LEN, NHEADS), 128>>>();

    // PV (triangular K): Y[:, h*128:] = P[h] @ (V^T)^T
    gemm_pk<<<dim3(1, 16, NHEADS), 256, GSMEM_BYTES>>>(ipq, 512, 1048576, ivt, 512, 65536, 2,
                                                       pfy, DMODEL, 128, 64, 1.0f, 4);

    // v-rejection -> packed y
    reject_kernel<<<(S_LEN * NHEADS) / 4, 128>>>();

    // output projection
    gemm_pk<<<dim3(16, 16, 1), 256, GSMEM_BYTES>>>(iyq, 512, 0, iwpq, 512, 0, 0,
                                                   out, DMODEL, 0, 64, 1.0f, 0);

    // v second output
    if (out_size >= S_LEN * DMODEL + S_LEN * KVD)
        v_transpose_kernel<<<(S_LEN * KVD / 4 + 255) / 256, 256>>>(out + (size_t)S_LEN * DMODEL);
}

// round 10
// speedup vs baseline: 2.2243x; 1.3805x over previous
#include <cuda_runtime.h>
#include <cuda_bf16.h>
#include <math.h>
#include <stdint.h>

#define S_LEN  2048
#define DMODEL 2048
#define NHEADS 16
#define HD     128
#define KVH    4
#define KVD    512
#define QKVW   3072   // 2048 q + 512 k + 512 v

// ---------------- fp32 intermediates ----------------
__device__ float g_qkv[S_LEN * QKVW];   // fused projection output

// ---------------- packed quad images ----------------
// Matrix [R][K] K-major: quad t = r*(K/32)*8 + ch*8 + q, q = ks*4+s,
// k0 = ch*32+ks*16+s*2; quad = {hi(k0,k0+1), hi(k0+8,k0+9), lo(..), lo(..)}.
__device__ uint4 xq_[1048576];     // x [2048][2048]
__device__ uint4 wqkvq_[1572864];  // [3072][2048]: Wq rows 0..2047, Wk 2048.., Wv 2560..
__device__ uint4 wpq_[1048576];
__device__ uint4 qq_[1048576];     // q roped*gain*scale, rows h*2048+s, K=128
__device__ uint4 kq_[262144];      // k roped, rows kv*2048+s, K=128
__device__ uint4 vtq_[262144];     // V^T, rows kv*128+d, K=2048
__device__ uint4 yq_[1048576];     // y rejected [2048][2048]

// ---------------- helpers ----------------
__device__ __forceinline__ void cvtpair(float x, float y, uint32_t& hi, uint32_t& lo) {
    __nv_bfloat16 hx = __float2bfloat16_rn(x);
    __nv_bfloat16 hy = __float2bfloat16_rn(y);
    float rx = x - __bfloat162float(hx);
    float ry = y - __bfloat162float(hy);
    __nv_bfloat16 lx = __float2bfloat16_rn(rx);
    __nv_bfloat16 ly = __float2bfloat16_rn(ry);
    hi = (uint32_t)__bfloat16_as_ushort(hx) | ((uint32_t)__bfloat16_as_ushort(hy) << 16);
    lo = (uint32_t)__bfloat16_as_ushort(lx) | ((uint32_t)__bfloat16_as_ushort(ly) << 16);
}

__device__ __forceinline__ uint4 pack_quad(float f0, float f1, float f2, float f3) {
    uint32_t h0, l0, h1, l1;
    cvtpair(f0, f1, h0, l0);
    cvtpair(f2, f3, h1, l1);
    return make_uint4(h0, h1, l0, l1);
}

__device__ __forceinline__ uint32_t s2u(const void* p) {
    uint32_t a;
    asm("{ .reg .u64 t; cvta.to.shared.u64 t, %1; cvt.u32.u64 %0, t; }" : "=r"(a) : "l"(p));
    return a;
}

__device__ __forceinline__ void cpa16(void* dst, const void* src) {
    asm volatile("cp.async.cg.shared.global [%0], [%1], 16;"
                 :: "r"(s2u(dst)), "l"(src) : "memory");
}
#define CPA_COMMIT() asm volatile("cp.async.commit_group;" ::: "memory")
#define CPA_WAIT0()  asm volatile("cp.async.wait_group 0;" ::: "memory")
#define CPA_WAIT1()  asm volatile("cp.async.wait_group 1;" ::: "memory")

__device__ __forceinline__ void mma_bf16(float* c, const uint32_t* a, const uint32_t* b) {
    asm volatile(
        "mma.sync.aligned.m16n8k16.row.col.f32.bf16.bf16.f32 "
        "{%0,%1,%2,%3}, {%4,%5,%6,%7}, {%8,%9}, {%0,%1,%2,%3};\n"
        : "+f"(c[0]), "+f"(c[1]), "+f"(c[2]), "+f"(c[3])
        : "r"(a[0]), "r"(a[1]), "r"(a[2]), "r"(a[3]),
          "r"(b[0]), "r"(b[1]));
}

// ---------------- generic K-major pack ----------------
__global__ void pack_mat(const float* __restrict__ src, int ldk,
                         uint4* __restrict__ dst, int nCh, int totalQ)
{
    int t = blockIdx.x * 256 + threadIdx.x;
    if (t >= totalQ) return;
    int rq = nCh * 8;
    int r = t / rq;
    int G = t - r * rq;
    int ch = G >> 3, q = G & 7;
    int k0 = ch * 32 + (q >> 2) * 16 + (q & 3) * 2;
    const float* p = src + (size_t)r * ldk + k0;
    dst[t] = pack_quad(p[0], p[1], p[8], p[9]);
}

// ---------------- V^T pack: rows kv*128+d, K = sequence ----------------
__global__ void pack_vt()
{
    int t = blockIdx.x * 256 + threadIdx.x;   // 262144
    int q = t & 7, ch = (t >> 3) & 63;
    int d = (t >> 9) & 127, kv = t >> 16;
    int k0 = ch * 32 + (q >> 2) * 16 + (q & 3) * 2;
    const float* p = g_qkv + (size_t)k0 * QKVW + 2560 + kv * HD + d;
    vtq_[t] = pack_quad(p[0], p[QKVW], p[8 * QKVW], p[9 * QKVW]);
}

// =============================================================
// bf16 3-pass GEMM, NT on packed images (validated R9 engine)
// =============================================================
#define SST 48
#define STAGE_U32 (2 * 128 * SST)
#define GSMEM_BYTES (2 * STAGE_U32 * 4)

__global__ void __launch_bounds__(256, 2)
gemm_pk(const uint4* __restrict__ Aq, int aRow, size_t aZ,
        const uint4* __restrict__ Bq, int bRow, size_t bZ, int bshift,
        float* __restrict__ C, int ldc, size_t cZ,
        int nChTot, float alpha, int mode)
{
    const int bm = blockIdx.y, bn = blockIdx.x, z = blockIdx.z;
    if ((mode & 2) && bn > bm) return;
    const int nCh = (mode & 4) ? min(nChTot, (bm + 1) * 4) : nChTot;

    extern __shared__ uint32_t smu[];
    const int tid = threadIdx.x, lane = tid & 31, wid = tid >> 5;
    const int wm = (wid >> 2) * 64, wn = (wid & 3) * 32;
    const int g8 = lane >> 2, tig = lane & 3;

    const uint4* Ab = Aq + z * aZ + (size_t)bm * 128 * aRow;
    const uint4* Bb = Bq + (size_t)(z >> bshift) * bZ + (size_t)bn * 128 * bRow;

    float acc[4][4][4] = {};

    auto loadStage = [&](int ch, int st) {
        uint32_t* base = smu + st * STAGE_U32;
#pragma unroll
        for (int i = 0; i < 8; i++) {
            int idx = tid + i * 256;
            int op = idx >> 10, rem = idx & 1023;
            int row = rem >> 3, q = rem & 7;
            const uint4* src = (op ? Bb + (size_t)row * bRow
                                   : Ab + (size_t)row * aRow) + ch * 8 + q;
            cpa16(base + op * (128 * SST) + row * SST + q * 4, src);
        }
        CPA_COMMIT();
    };

    auto compute = [&](int st) {
        const uint32_t* As = smu + st * STAGE_U32;
        const uint32_t* Bs = As + 128 * SST;
#pragma unroll
        for (int g = 0; g < 2; g++) {
            uint32_t aH[4][4], aL[4][4], bH[4][2], bL[4][2];
#pragma unroll
            for (int mf = 0; mf < 4; mf++) {
                int r0 = wm + mf * 16 + g8;
                uint4 q0 = *(const uint4*)(As + r0 * SST + g * 16 + tig * 4);
                uint4 q1 = *(const uint4*)(As + (r0 + 8) * SST + g * 16 + tig * 4);
                aH[mf][0] = q0.x; aH[mf][1] = q1.x; aH[mf][2] = q0.y; aH[mf][3] = q1.y;
                aL[mf][0] = q0.z; aL[mf][1] = q1.z; aL[mf][2] = q0.w; aL[mf][3] = q1.w;
            }
#pragma unroll
            for (int nf = 0; nf < 4; nf++) {
                int n = wn + nf * 8 + g8;
                uint4 q = *(const uint4*)(Bs + n * SST + g * 16 + tig * 4);
                bH[nf][0] = q.x; bH[nf][1] = q.y;
                bL[nf][0] = q.z; bL[nf][1] = q.w;
            }
#pragma unroll
            for (int mf = 0; mf < 4; mf++)
#pragma unroll
                for (int nf = 0; nf < 4; nf++) {
                    mma_bf16(acc[mf][nf], aL[mf], bH[nf]);
                    mma_bf16(acc[mf][nf], aH[mf], bL[nf]);
                    mma_bf16(acc[mf][nf], aH[mf], bH[nf]);
                }
        }
    };

    loadStage(0, 0);
    for (int it = 0; it < nCh; ++it) {
        int cur = it & 1;
        if (it + 1 < nCh) { loadStage(it + 1, cur ^ 1); CPA_WAIT1(); }
        else              { CPA_WAIT0(); }
        __syncthreads();
        compute(cur);
        __syncthreads();
    }

    float* Cb = C + z * cZ + (size_t)bm * 128 * ldc + bn * 128;
#pragma unroll
    for (int mf = 0; mf < 4; mf++) {
        int row0 = wm + mf * 16 + g8, row1 = row0 + 8;
#pragma unroll
        for (int nf = 0; nf < 4; nf++) {
            int col = wn + nf * 8 + tig * 2;
            *(float2*)(Cb + (size_t)row0 * ldc + col) =
                make_float2(acc[mf][nf][0] * alpha, acc[mf][nf][1] * alpha);
            *(float2*)(Cb + (size_t)row1 * ldc + col) =
                make_float2(acc[mf][nf][2] * alpha, acc[mf][nf][3] * alpha);
        }
    }
}

// ---------------- RMSNorm + RoPE -> packed image ----------------
__global__ void rope2_kernel(const float* __restrict__ buf, int rowstride, int nheads,
                             const float* __restrict__ gain, float outscale,
                             uint4* __restrict__ img)
{
    __shared__ float stg[4][128];
    const int wib = threadIdx.x >> 5;
    const int w = blockIdx.x * 4 + wib;
    const int lane = threadIdx.x & 31;
    const int s = w / nheads, h = w % nheads;
    if (s >= S_LEN) return;

    const float* p = buf + (size_t)s * rowstride + h * HD;
    float2 u1 = *(const float2*)(p + 2 * lane);
    float2 u2 = *(const float2*)(p + 64 + 2 * lane);
    float ss = u1.x * u1.x + u1.y * u1.y + u2.x * u2.x + u2.y * u2.y;
#pragma unroll
    for (int off = 16; off; off >>= 1) ss += __shfl_xor_sync(0xffffffffu, ss, off);
    const float r = rsqrtf(ss * (1.f / 128.f) + 1.1920929e-07f);
    const float g = (gain ? gain[h] : 1.0f) * outscale;
    float x1a = u1.x * r, x1b = u1.y * r, x2a = u2.x * r, x2b = u2.y * r;
    const float kln = 9.210340371976184f / 128.f;
    float th0 = (float)s * expf(-(float)(4 * lane) * kln);
    float th1 = (float)s * expf(-(float)(4 * lane + 2) * kln);
    float c0, s0, c1, s1;
    sincosf(th0, &s0, &c0);
    sincosf(th1, &s1, &c1);
    stg[wib][2 * lane]          = (x1a * c0 + x2a * s0) * g;
    stg[wib][2 * lane + 1]      = (x1b * c1 + x2b * s1) * g;
    stg[wib][64 + 2 * lane]     = (x2a * c0 - x1a * s0) * g;
    stg[wib][64 + 2 * lane + 1] = (x2b * c1 - x1b * s1) * g;
    __syncwarp();
    int ch = lane >> 3, q = lane & 7;
    int k0 = ch * 32 + (q >> 2) * 16 + (q & 3) * 2;
    const float* sp = &stg[wib][0];
    img[(size_t)(h * S_LEN + s) * 32 + lane] =
        pack_quad(sp[k0], sp[k0 + 1], sp[k0 + 8], sp[k0 + 9]);
}

// =============================================================
// Fused flash attention + v-rejection + y pack.
// CTA = (q-tile 128 rows, head). 8 warps, warp = 16 rows x full width.
// Smem: sQ 64KB | sK 64KB | sV 64KB (packed quads). 3-pass mma both GEMMs.
// =============================================================
#define FL_SMEM (3 * 4096 * 16)

__global__ void __launch_bounds__(256, 1)
flash_attn()
{
    extern __shared__ uint4 fsm[];
    uint4* sQ = fsm;
    uint4* sK = fsm + 4096;
    uint4* sV = fsm + 8192;

    const int bid = blockIdx.x;
    const int qb = 15 - (bid >> 4);       // heavy tiles first
    const int h  = bid & 15;
    const int kv = h >> 2;
    const int tid = threadIdx.x, lane = tid & 31, wid = tid >> 5;
    const int g8 = lane >> 2, tig = lane & 3;
    const int mr = wid * 16;

    // ---- load Q tile + K(0) tile ----
    {
        const uint4* Qg = qq_ + ((size_t)h * S_LEN + qb * 128) * 32;
        const uint4* Kg = kq_ + ((size_t)kv * S_LEN) * 32;
#pragma unroll
        for (int i = 0; i < 16; i++) { int idx = tid + i * 256; cpa16(&sQ[idx], &Qg[idx]); }
#pragma unroll
        for (int i = 0; i < 16; i++) { int idx = tid + i * 256; cpa16(&sK[idx], &Kg[idx]); }
        CPA_COMMIT(); CPA_WAIT0(); __syncthreads();
    }

    float sAcc[16][4];
    float oAcc[16][4] = {};
    float mA = -INFINITY, mB = -INFINITY, lA = 0.f, lB = 0.f;

    for (int kb = 0; kb <= qb; kb++) {
        // prefetch V(kb) during QK^T
#pragma unroll
        for (int i = 0; i < 16; i++) {
            int idx = tid + i * 256;
            int row = idx >> 5, lq = idx & 31;
            cpa16(&sV[row * 32 + lq],
                  &vtq_[((size_t)(kv * 128 + row)) * 512 + kb * 32 + lq]);
        }
        CPA_COMMIT();

        // ---- S = Q K^T (3-pass) ----
#pragma unroll
        for (int nf = 0; nf < 16; nf++)
#pragma unroll
            for (int e = 0; e < 4; e++) sAcc[nf][e] = 0.f;
#pragma unroll
        for (int c = 0; c < 8; c++) {
            int qoff = (c >> 1) * 8 + (c & 1) * 4 + tig;
            uint4 q0 = sQ[(mr + g8) * 32 + qoff];
            uint4 q1 = sQ[(mr + g8 + 8) * 32 + qoff];
            uint32_t aH[4] = {q0.x, q1.x, q0.y, q1.y};
            uint32_t aL[4] = {q0.z, q1.z, q0.w, q1.w};
#pragma unroll
            for (int nf = 0; nf < 16; nf++) {
                uint4 kq4 = sK[(nf * 8 + g8) * 32 + qoff];
                uint32_t bH[2] = {kq4.x, kq4.y}, bL[2] = {kq4.z, kq4.w};
                mma_bf16(sAcc[nf], aL, bH);
                mma_bf16(sAcc[nf], aH, bL);
                mma_bf16(sAcc[nf], aH, bH);
            }
        }

        // ---- causal mask on diagonal tile ----
        if (kb == qb) {
            int rA = mr + g8, rB = rA + 8;
#pragma unroll
            for (int nf = 0; nf < 16; nf++) {
                int c0 = nf * 8 + tig * 2;
                if (c0     > rA) sAcc[nf][0] = -INFINITY;
                if (c0 + 1 > rA) sAcc[nf][1] = -INFINITY;
                if (c0     > rB) sAcc[nf][2] = -INFINITY;
                if (c0 + 1 > rB) sAcc[nf][3] = -INFINITY;
            }
        }

        // ---- online softmax ----
        float mlA = -INFINITY, mlB = -INFINITY;
#pragma unroll
        for (int nf = 0; nf < 16; nf++) {
            mlA = fmaxf(mlA, fmaxf(sAcc[nf][0], sAcc[nf][1]));
            mlB = fmaxf(mlB, fmaxf(sAcc[nf][2], sAcc[nf][3]));
        }
        mlA = fmaxf(mlA, __shfl_xor_sync(0xffffffffu, mlA, 1));
        mlA = fmaxf(mlA, __shfl_xor_sync(0xffffffffu, mlA, 2));
        mlB = fmaxf(mlB, __shfl_xor_sync(0xffffffffu, mlB, 1));
        mlB = fmaxf(mlB, __shfl_xor_sync(0xffffffffu, mlB, 2));
        float mnA = fmaxf(mA, mlA), mnB = fmaxf(mB, mlB);
        float alA = __expf(mA - mnA), alB = __expf(mB - mnB);
        mA = mnA; mB = mnB;
        float rsA = 0.f, rsB = 0.f;
#pragma unroll
        for (int nf = 0; nf < 16; nf++) {
            float p0 = __expf(sAcc[nf][0] - mnA);
            float p1 = __expf(sAcc[nf][1] - mnA);
            float p2 = __expf(sAcc[nf][2] - mnB);
            float p3 = __expf(sAcc[nf][3] - mnB);
            sAcc[nf][0] = p0; sAcc[nf][1] = p1; sAcc[nf][2] = p2; sAcc[nf][3] = p3;
            rsA += p0 + p1; rsB += p2 + p3;
        }
        rsA += __shfl_xor_sync(0xffffffffu, rsA, 1);
        rsA += __shfl_xor_sync(0xffffffffu, rsA, 2);
        rsB += __shfl_xor_sync(0xffffffffu, rsB, 1);
        rsB += __shfl_xor_sync(0xffffffffu, rsB, 2);
        lA = lA * alA + rsA;
        lB = lB * alB + rsB;
#pragma unroll
        for (int nf = 0; nf < 16; nf++) {
            oAcc[nf][0] *= alA; oAcc[nf][1] *= alA;
            oAcc[nf][2] *= alB; oAcc[nf][3] *= alB;
        }

        // V ready; K consumed
        CPA_WAIT0(); __syncthreads();

        // prefetch K(kb+1) during PV
        if (kb < qb) {
            const uint4* Kg = kq_ + ((size_t)kv * S_LEN + (kb + 1) * 128) * 32;
#pragma unroll
            for (int i = 0; i < 16; i++) { int idx = tid + i * 256; cpa16(&sK[idx], &Kg[idx]); }
            CPA_COMMIT();
        }

        // ---- O += P V (3-pass; P hi/lo from fp32 frags) ----
#pragma unroll
        for (int c = 0; c < 8; c++) {
            uint32_t aH[4], aL[4];
            cvtpair(sAcc[2 * c][0],     sAcc[2 * c][1],     aH[0], aL[0]);
            cvtpair(sAcc[2 * c][2],     sAcc[2 * c][3],     aH[1], aL[1]);
            cvtpair(sAcc[2 * c + 1][0], sAcc[2 * c + 1][1], aH[2], aL[2]);
            cvtpair(sAcc[2 * c + 1][2], sAcc[2 * c + 1][3], aH[3], aL[3]);
            int qoff = (c >> 1) * 8 + (c & 1) * 4 + tig;
#pragma unroll
            for (int nf = 0; nf < 16; nf++) {
                uint4 v4 = sV[(nf * 8 + g8) * 32 + qoff];
                uint32_t bH[2] = {v4.x, v4.y}, bL[2] = {v4.z, v4.w};
                mma_bf16(oAcc[nf], aL, bH);
                mma_bf16(oAcc[nf], aH, bL);
                mma_bf16(oAcc[nf], aH, bH);
            }
        }

        if (kb < qb) { CPA_WAIT0(); __syncthreads(); }
    }

    // ---- epilogue: normalize, stage to smem, reject, pack ----
    __syncthreads();
    float* Ob = (float*)sK;   // 128 rows x 132 stride fp32 (spans sK+sV)
    float invA = 1.f / lA, invB = 1.f / lB;
#pragma unroll
    for (int nf = 0; nf < 16; nf++) {
        int col = nf * 8 + tig * 2;
        Ob[(mr + g8) * 132 + col]         = oAcc[nf][0] * invA;
        Ob[(mr + g8) * 132 + col + 1]     = oAcc[nf][1] * invA;
        Ob[(mr + g8 + 8) * 132 + col]     = oAcc[nf][2] * invB;
        Ob[(mr + g8 + 8) * 132 + col + 1] = oAcc[nf][3] * invB;
    }
    __syncthreads();

    const float* gv = g_qkv + 2560 + kv * HD;
    for (int r16 = 0; r16 < 16; r16++) {
        int r = mr + r16;
        int sg = qb * 128 + r;
        float4 vv = *(const float4*)(gv + (size_t)sg * QKVW + lane * 4);
        float4 yy = *(float4*)(Ob + r * 132 + lane * 4);
        float vsq = vv.x * vv.x + vv.y * vv.y + vv.z * vv.z + vv.w * vv.w;
        float yv  = yy.x * vv.x + yy.y * vv.y + yy.z * vv.z + yy.w * vv.w;
#pragma unroll
        for (int off = 16; off; off >>= 1) {
            vsq += __shfl_xor_sync(0xffffffffu, vsq, off);
            yv  += __shfl_xor_sync(0xffffffffu, yv, off);
        }
        float mx = fmaxf(sqrtf(vsq), 1e-12f);
        float c2 = yv / (mx * mx);
        yy.x -= c2 * vv.x; yy.y -= c2 * vv.y; yy.z -= c2 * vv.z; yy.w -= c2 * vv.w;
        *(float4*)(Ob + r * 132 + lane * 4) = yy;
        __syncwarp();
        int ch = lane >> 3, ks = (lane >> 2) & 1, sq = lane & 3;
        int k0 = ch * 32 + ks * 16 + sq * 2;
        yq_[(size_t)sg * 512 + (h * 4 + ch) * 8 + ks * 4 + sq] =
            pack_quad(Ob[r * 132 + k0], Ob[r * 132 + k0 + 1],
                      Ob[r * 132 + k0 + 8], Ob[r * 132 + k0 + 9]);
        __syncwarp();
    }
}

// ---------------- v output transpose ----------------
__global__ void v_transpose_kernel(float* __restrict__ out)
{
    int idx = blockIdx.x * blockDim.x + threadIdx.x;
    if (idx < S_LEN * KVD / 4) {
        int f = idx * 4;
        int s = f / KVD, rem = f % KVD;
        int kvh = rem / HD, d = rem % HD;
        float4 val = *(const float4*)(g_qkv + (size_t)s * QKVW + 2560 + kvh * HD + d);
        *(float4*)(out + (size_t)kvh * S_LEN * HD + (size_t)s * HD + d) = val;
    }
}

// ---------------- launch ----------------
extern "C" void kernel_launch(void* const* d_in, const int* in_sizes, int n_in,
                              void* d_out, int out_size)
{
    int big[3], nbig = 0, med[2], nmed = 0, gidx = -1;
    for (int i = 0; i < n_in && i < 6; i++) {
        int sz = in_sizes[i];
        if (sz == NHEADS) gidx = i;
        else if (sz == S_LEN * KVD) { if (nmed < 2) med[nmed++] = i; }
        else { if (nbig < 3) big[nbig++] = i; }
    }
    int ix, iwq, iwk, iwv, iwp, ig;
    ig  = (gidx >= 0) ? gidx : 5;
    iwk = (nmed > 0) ? med[0] : 2;
    iwv = (nmed > 1) ? med[1] : 3;
    if (ig == 5) { ix = big[0]; iwq = big[1]; iwp = big[2]; }
    else         { iwp = big[0]; iwq = big[1]; ix = big[2]; }

    const float* x  = (const float*)d_in[ix];
    const float* Wq = (const float*)d_in[iwq];
    const float* Wk = (const float*)d_in[iwk];
    const float* Wv = (const float*)d_in[iwv];
    const float* Wp = (const float*)d_in[iwp];
    const float* qg = (const float*)d_in[ig];
    float* out = (float*)d_out;

    float* pqkv;
    cudaGetSymbolAddress((void**)&pqkv, g_qkv);
    uint4 *ixq, *iwqkv, *iwpq, *iqq, *ikq, *ivt, *iyq;
    cudaGetSymbolAddress((void**)&ixq,   xq_);
    cudaGetSymbolAddress((void**)&iwqkv, wqkvq_);
    cudaGetSymbolAddress((void**)&iwpq,  wpq_);
    cudaGetSymbolAddress((void**)&iqq,   qq_);
    cudaGetSymbolAddress((void**)&ikq,   kq_);
    cudaGetSymbolAddress((void**)&ivt,   vtq_);
    cudaGetSymbolAddress((void**)&iyq,   yq_);

    cudaFuncSetAttribute(gemm_pk, cudaFuncAttributeMaxDynamicSharedMemorySize, GSMEM_BYTES);
    cudaFuncSetAttribute(flash_attn, cudaFuncAttributeMaxDynamicSharedMemorySize, FL_SMEM);
    (void)cudaGetLastError();

    const float scale = 0.08838834764831845f;   // 1/sqrt(128)

    // one-time packs (Wq/Wk/Wv into one 3072-row image)
    pack_mat<<<4096, 256>>>(x,  DMODEL, ixq, 64, 1048576);
    pack_mat<<<4096, 256>>>(Wq, DMODEL, iwqkv, 64, 1048576);
    pack_mat<<<1024, 256>>>(Wk, DMODEL, iwqkv + (size_t)2048 * 512, 64, 262144);
    pack_mat<<<1024, 256>>>(Wv, DMODEL, iwqkv + (size_t)2560 * 512, 64, 262144);
    pack_mat<<<4096, 256>>>(Wp, DMODEL, iwpq, 64, 1048576);

    // fused QKV projection (NT): g_qkv = x @ [Wq;Wk;Wv]^T
    gemm_pk<<<dim3(24, 16, 1), 256, GSMEM_BYTES>>>(ixq, 512, 0, iwqkv, 512, 0, 0,
                                                   pqkv, QKVW, 0, 64, 1.0f, 0);

    // rmsnorm + rope -> packed q (gain*scale folded) / k ; V^T pack
    rope2_kernel<<<(S_LEN * NHEADS) / 4, 128>>>(pqkv, QKVW, NHEADS, qg, scale, iqq);
    rope2_kernel<<<(S_LEN * KVH) / 4, 128>>>(pqkv + 2048, QKVW, KVH, nullptr, 1.0f, ikq);
    pack_vt<<<1024, 256>>>();

    // fused flash attention (+ v-rejection + y pack)
    flash_attn<<<256, 256, FL_SMEM>>>();

    // output projection
    gemm_pk<<<dim3(16, 16, 1), 256, GSMEM_BYTES>>>(iyq, 512, 0, iwpq, 512, 0, 0,
                                                   out, DMODEL, 0, 64, 1.0f, 0);

    // v second output
    if (out_size >= S_LEN * DMODEL + S_LEN * KVD)
        v_transpose_kernel<<<(S_LEN * KVD / 4 + 255) / 256, 256>>>(out + (size_t)S_LEN * DMODEL);
}